// round 10
// baseline (speedup 1.0000x reference)
#include <cuda_runtime.h>
#include <cuda_bf16.h>
#include <cstdint>
#include <cstddef>

#define VOCAB 32000
#define EMB   32
#define REC   16
#define SEQ   256
#define BATCH 32

#define NT8 (VOCAB / 8)              // 4000 vocab n-tiles of 8 rows

// pass A (sumexp): 10 slices -> 400 tiles/CTA, 50/warp
#define SLICES_A 10
#define TPC_A    (NT8 / SLICES_A)
#define TPW_A    (TPC_A / 8)
// pass B (write): 20 slices -> 200 tiles/CTA, 25/warp
#define SLICES_B 20
#define TPC_B    (NT8 / SLICES_B)
#define TPW_B    (TPC_B / 8)

// Scratch (allocation-free rule: __device__ globals)
__device__ float g_hidden[SEQ * BATCH * REC];
__device__ float g_iproj [SEQ * BATCH * REC];
__device__ float g_sumexp[SEQ * BATCH];
__device__ uint2 g_Vmma  [NT8 * 32];   // V as B-operand fragments, lane-ordered

// ---------------------------------------------------------------------------
// helpers
// ---------------------------------------------------------------------------
__device__ __forceinline__ float2 ffma2(float2 a, float2 b, float2 c) {
    union { float2 f; unsigned long long u; } A, B, C, D;
    A.f = a; B.f = b; C.f = c;
    asm("fma.rn.f32x2 %0, %1, %2, %3;" : "=l"(D.u) : "l"(A.u), "l"(B.u), "l"(C.u));
    return D.f;
}

__device__ __forceinline__ uint32_t pk2(float a, float b) {
    __nv_bfloat162 t = __float22bfloat162_rn(make_float2(a, b));
    return *reinterpret_cast<uint32_t*>(&t);
}

// D(16x8,f32) = A(16x16,bf16,row) * B(16x8,bf16,col) + D   — base-ISA HMMA
// M rows = batch, N cols = vocab.
__device__ __forceinline__ void mma16816(float* d, const uint32_t* a,
                                         uint32_t b0, uint32_t b1) {
    asm volatile(
        "mma.sync.aligned.m16n8k16.row.col.f32.bf16.bf16.f32 "
        "{%0,%1,%2,%3}, {%4,%5,%6,%7}, {%8,%9}, {%0,%1,%2,%3};"
        : "+f"(d[0]), "+f"(d[1]), "+f"(d[2]), "+f"(d[3])
        : "r"(a[0]), "r"(a[1]), "r"(a[2]), "r"(a[3]), "r"(b0), "r"(b1));
}

// ---------------------------------------------------------------------------
// Kernel 0: pack V into B-operand fragments.
// Vocab n-tile = 8 rows. Lane (g=lane>>2, t=lane&3) holds for vocab row
// r = 8*tile+g:  b.x = {V[r][2t],V[r][2t+1]}, b.y = {V[r][2t+8],V[r][2t+9]}.
// ---------------------------------------------------------------------------
__global__ void vprep_kernel(const float* __restrict__ V) {
    int idx = blockIdx.x * blockDim.x + threadIdx.x;
    if (idx >= NT8 * 32) return;
    int tile = idx >> 5, lane = idx & 31;
    int g = lane >> 2, t = lane & 3;
    const float* r = V + (size_t)(tile * 8 + g) * REC;
    uint2 b;
    b.x = pk2(r[2 * t],     r[2 * t + 1]);
    b.y = pk2(r[2 * t + 8], r[2 * t + 9]);
    g_Vmma[idx] = b;
}

// ---------------------------------------------------------------------------
// Kernel 1: input projection + zero g_sumexp.
// ---------------------------------------------------------------------------
__global__ void iproj_kernel(const int* __restrict__ tok,
                             const float* __restrict__ emb,
                             const float* __restrict__ U,
                             const float* __restrict__ b1,
                             const float* __restrict__ b2) {
    int idx = blockIdx.x * blockDim.x + threadIdx.x;
    if (idx < SEQ * BATCH) g_sumexp[idx] = 0.0f;
    if (idx >= SEQ * BATCH * REC) return;
    int r  = idx & (REC - 1);
    int sb = idx >> 4;
    int t  = tok[sb];
    const float4* e = (const float4*)(emb + (size_t)t * EMB);
    const float4* u = (const float4*)(U + (size_t)r * EMB);
    float acc = b1[r] + b2[r];
#pragma unroll
    for (int q = 0; q < EMB / 4; q++) {
        float4 ev = e[q], uv = u[q];
        acc = fmaf(ev.x, uv.x, acc);
        acc = fmaf(ev.y, uv.y, acc);
        acc = fmaf(ev.z, uv.z, acc);
        acc = fmaf(ev.w, uv.w, acc);
    }
    g_iproj[idx] = acc;
}

// ---------------------------------------------------------------------------
// Kernel 2: sequential recurrence (single CTA), unchanged.
// ---------------------------------------------------------------------------
__global__ void __launch_bounds__(256) rnn_kernel(const float* __restrict__ W,
                                                  const float* __restrict__ h0) {
    __shared__ float2 hd[2][REC][17];
    int tid = threadIdx.x;
    int bp  = tid >> 4;
    int r   = tid & (REC - 1);

    float2 wdup[REC];
#pragma unroll
    for (int j = 0; j < REC; j++) {
        float w = W[r * REC + j];
        wdup[j] = make_float2(w, w);
    }

    float c0 = h0[r], c1 = c0;
    hd[0][r][bp] = make_float2(c0, c1);
    __syncthreads();

    const int base = bp * 2 * REC + r;

    float ip0[2], ip1[2];
    ip0[0] = g_iproj[0 * 512 + base];  ip1[0] = g_iproj[0 * 512 + base + REC];
    ip0[1] = g_iproj[1 * 512 + base];  ip1[1] = g_iproj[1 * 512 + base + REC];

    for (int t = 0; t < SEQ; t++) {
        g_hidden[t * 512 + base]       = c0;
        g_hidden[t * 512 + base + REC] = c1;

        if (t < SEQ - 1) {
            int rb = t & 1, wb = rb ^ 1;
            float2 acc = make_float2(ip0[rb], ip1[rb]);
            if (t + 2 < SEQ) {
                ip0[rb] = g_iproj[(t + 2) * 512 + base];
                ip1[rb] = g_iproj[(t + 2) * 512 + base + REC];
            }
#pragma unroll
            for (int j = 0; j < REC; j++)
                acc = ffma2(hd[rb][j][bp], wdup[j], acc);
            float e0 = __expf(2.0f * acc.x);
            float e1 = __expf(2.0f * acc.y);
            c0 = 1.0f - __fdividef(2.0f, e0 + 1.0f);
            c1 = 1.0f - __fdividef(2.0f, e1 + 1.0f);
            hd[wb][r][bp] = make_float2(c0, c1);
        }
        __syncthreads();
    }
}

// Build A fragments (h, batch-as-M): 2 m-tiles (batch 0-15, 16-31).
// Lane (g,t): a[m] = { {h[m16+g][2t..]}, {h[m16+g+8][2t..]},
//                     {h[m16+g][2t+8..]}, {h[m16+g+8][2t+8..]} }
__device__ __forceinline__ void make_afrags(uint32_t a[2][4], int s, int g, int t) {
    const float* hb = g_hidden + s * 512;
#pragma unroll
    for (int m = 0; m < 2; m++) {
        int r0 = m * 16 + g, r1 = m * 16 + g + 8;
        float2 x0 = *(const float2*)(hb + r0 * REC + 2 * t);
        float2 x1 = *(const float2*)(hb + r1 * REC + 2 * t);
        float2 x2 = *(const float2*)(hb + r0 * REC + 2 * t + 8);
        float2 x3 = *(const float2*)(hb + r1 * REC + 2 * t + 8);
        a[m][0] = pk2(x0.x, x0.y);
        a[m][1] = pk2(x1.x, x1.y);
        a[m][2] = pk2(x2.x, x2.y);
        a[m][3] = pk2(x3.x, x3.y);
    }
}

// ---------------------------------------------------------------------------
// Kernel 3a: sum of exp(logit). grid(SLICES_A, SEQ), 256 threads.
// D lane (g,t) = batch rows {g, g+8} (+16 for m-tile 1), vocab cols 2t,2t+1.
// ---------------------------------------------------------------------------
__global__ void __launch_bounds__(256) sumexp_mma_kernel() {
    const int slice = blockIdx.x;
    const int s     = blockIdx.y;
    const int tid   = threadIdx.x;
    const int wid   = tid >> 5, lane = tid & 31;
    const int g = lane >> 2, t = lane & 3;

    uint32_t a[2][4];
    make_afrags(a, s, g, t);

    float acc[4] = {0.f, 0.f, 0.f, 0.f};   // batch rows g, g+8, g+16, g+24

    const int tile0 = slice * TPC_A + wid * TPW_A;
    const uint2* bp = &g_Vmma[(size_t)tile0 * 32 + lane];

    for (int i = 0; i < TPW_A; i++) {
        uint2 b = bp[i * 32];
        float d0[4] = {0.f, 0.f, 0.f, 0.f};
        float d1[4] = {0.f, 0.f, 0.f, 0.f};
        mma16816(d0, a[0], b.x, b.y);
        mma16816(d1, a[1], b.x, b.y);
        acc[0] += __expf(d0[0]) + __expf(d0[1]);
        acc[1] += __expf(d0[2]) + __expf(d0[3]);
        acc[2] += __expf(d1[0]) + __expf(d1[1]);
        acc[3] += __expf(d1[2]) + __expf(d1[3]);
    }

    // reduce over t (lanes xor 1, 2)
#pragma unroll
    for (int k = 0; k < 4; k++) {
        float v = acc[k];
        v += __shfl_xor_sync(0xffffffffu, v, 1);
        v += __shfl_xor_sync(0xffffffffu, v, 2);
        acc[k] = v;
    }

    __shared__ float red[8][BATCH];
    if (t == 0) {
        red[wid][g]      = acc[0];
        red[wid][g + 8]  = acc[1];
        red[wid][g + 16] = acc[2];
        red[wid][g + 24] = acc[3];
    }
    __syncthreads();
    if (tid < BATCH) {
        float tot = 0.f;
#pragma unroll
        for (int w = 0; w < 8; w++) tot += red[w][tid];
        atomicAdd(&g_sumexp[s * BATCH + tid], tot);
    }
}

// ---------------------------------------------------------------------------
// Kernel 3b: recompute logits, write log_softmax. grid(SLICES_B, SEQ).
// Accumulators initialized to -logZ (the subtract folds into the MMA).
// Each thread stores float2 of adjacent vocab values -> STG.64.
// ---------------------------------------------------------------------------
__global__ void __launch_bounds__(256) write_mma_kernel(float* __restrict__ out) {
    const int slice = blockIdx.x;
    const int s     = blockIdx.y;
    const int tid   = threadIdx.x;
    const int wid   = tid >> 5, lane = tid & 31;
    const int g = lane >> 2, t = lane & 3;

    uint32_t a[2][4];
    make_afrags(a, s, g, t);

    const float* se = g_sumexp + s * BATCH;
    const float nz0 = -__logf(se[g]);
    const float nz1 = -__logf(se[g + 8]);
    const float nz2 = -__logf(se[g + 16]);
    const float nz3 = -__logf(se[g + 24]);

    const int tile0 = slice * TPC_B + wid * TPW_B;
    const uint2* bp = &g_Vmma[(size_t)tile0 * 32 + lane];
    float* obase = out + (size_t)s * BATCH * VOCAB;

    float* p0 = obase + (size_t)(g)      * VOCAB + tile0 * 8 + 2 * t;
    float* p1 = obase + (size_t)(g + 8)  * VOCAB + tile0 * 8 + 2 * t;
    float* p2 = obase + (size_t)(g + 16) * VOCAB + tile0 * 8 + 2 * t;
    float* p3 = obase + (size_t)(g + 24) * VOCAB + tile0 * 8 + 2 * t;

    for (int i = 0; i < TPW_B; i++) {
        uint2 b = bp[i * 32];
        float d0[4] = {nz0, nz0, nz1, nz1};
        float d1[4] = {nz2, nz2, nz3, nz3};
        mma16816(d0, a[0], b.x, b.y);
        mma16816(d1, a[1], b.x, b.y);
        *(float2*)(p0 + i * 8) = make_float2(d0[0], d0[1]);
        *(float2*)(p1 + i * 8) = make_float2(d0[2], d0[3]);
        *(float2*)(p2 + i * 8) = make_float2(d1[0], d1[1]);
        *(float2*)(p3 + i * 8) = make_float2(d1[2], d1[3]);
    }
}

// ---------------------------------------------------------------------------
extern "C" void kernel_launch(void* const* d_in, const int* in_sizes, int n_in,
                              void* d_out, int out_size) {
    const int*   tok = (const int*)  d_in[0];
    const float* emb = (const float*)d_in[1];
    const float* U   = (const float*)d_in[2];
    const float* W   = (const float*)d_in[3];
    const float* V   = (const float*)d_in[4];
    const float* b1  = (const float*)d_in[5];
    const float* b2  = (const float*)d_in[6];
    const float* h0  = (const float*)d_in[7];
    float* out = (float*)d_out;

    vprep_kernel<<<(NT8 * 32 + 255) / 256, 256>>>(V);
    iproj_kernel<<<(SEQ * BATCH * REC + 255) / 256, 256>>>(tok, emb, U, b1, b2);
    rnn_kernel<<<1, 256>>>(W, h0);
    dim3 gridA(SLICES_A, SEQ);
    sumexp_mma_kernel<<<gridA, 256>>>();
    dim3 gridB(SLICES_B, SEQ);
    write_mma_kernel<<<gridB, 256>>>(out);
}

// round 12
// speedup vs baseline: 1.1312x; 1.1312x over previous
#include <cuda_runtime.h>
#include <cuda_bf16.h>
#include <cstdint>
#include <cstddef>

#define VOCAB 32000
#define EMB   32
#define REC   16
#define SEQ   256
#define BATCH 32

#define NT8 (VOCAB / 8)              // 4000 vocab n-tiles of 8 rows

// pass A (sumexp): 10 slices -> 400 tiles/CTA, 50/warp
#define SLICES_A 10
#define TPC_A    (NT8 / SLICES_A)
#define TPW_A    (TPC_A / 8)

// pass B (write): chunks of 32 vocab (4 n-tiles). 1000 chunks per s.
#define NCHUNKS   (VOCAB / 32)       // 1000
#define SLICES_B  25
#define CPC_B     (NCHUNKS / SLICES_B)   // 40 chunks/CTA
#define CPW_B     (CPC_B / 8)            // 5 chunks/warp

// Scratch (allocation-free rule: __device__ globals)
__device__ float g_hidden[SEQ * BATCH * REC];
__device__ float g_iproj [SEQ * BATCH * REC];
__device__ float g_sumexp[SEQ * BATCH];
__device__ uint2 g_Vmma  [NT8 * 32];   // V as B-operand fragments, lane-ordered

// ---------------------------------------------------------------------------
// helpers
// ---------------------------------------------------------------------------
__device__ __forceinline__ float2 ffma2(float2 a, float2 b, float2 c) {
    union { float2 f; unsigned long long u; } A, B, C, D;
    A.f = a; B.f = b; C.f = c;
    asm("fma.rn.f32x2 %0, %1, %2, %3;" : "=l"(D.u) : "l"(A.u), "l"(B.u), "l"(C.u));
    return D.f;
}

__device__ __forceinline__ uint32_t pk2(float a, float b) {
    __nv_bfloat162 t = __float22bfloat162_rn(make_float2(a, b));
    return *reinterpret_cast<uint32_t*>(&t);
}

// D(16x8,f32) = A(16x16,bf16,row) * B(16x8,bf16,col) + D   — base-ISA HMMA
// M rows = batch, N cols = vocab.
__device__ __forceinline__ void mma16816(float* d, const uint32_t* a,
                                         uint32_t b0, uint32_t b1) {
    asm volatile(
        "mma.sync.aligned.m16n8k16.row.col.f32.bf16.bf16.f32 "
        "{%0,%1,%2,%3}, {%4,%5,%6,%7}, {%8,%9}, {%0,%1,%2,%3};"
        : "+f"(d[0]), "+f"(d[1]), "+f"(d[2]), "+f"(d[3])
        : "r"(a[0]), "r"(a[1]), "r"(a[2]), "r"(a[3]), "r"(b0), "r"(b1));
}

// ---------------------------------------------------------------------------
// Kernel 0: pack V into B-operand fragments.
// Vocab n-tile = 8 rows. Lane (g=lane>>2, t=lane&3) holds for vocab row
// r = 8*tile+g:  b.x = {V[r][2t],V[r][2t+1]}, b.y = {V[r][2t+8],V[r][2t+9]}.
// ---------------------------------------------------------------------------
__global__ void vprep_kernel(const float* __restrict__ V) {
    int idx = blockIdx.x * blockDim.x + threadIdx.x;
    if (idx >= NT8 * 32) return;
    int tile = idx >> 5, lane = idx & 31;
    int g = lane >> 2, t = lane & 3;
    const float* r = V + (size_t)(tile * 8 + g) * REC;
    uint2 b;
    b.x = pk2(r[2 * t],     r[2 * t + 1]);
    b.y = pk2(r[2 * t + 8], r[2 * t + 9]);
    g_Vmma[idx] = b;
}

// ---------------------------------------------------------------------------
// Kernel 1: input projection + zero g_sumexp.
// ---------------------------------------------------------------------------
__global__ void iproj_kernel(const int* __restrict__ tok,
                             const float* __restrict__ emb,
                             const float* __restrict__ U,
                             const float* __restrict__ b1,
                             const float* __restrict__ b2) {
    int idx = blockIdx.x * blockDim.x + threadIdx.x;
    if (idx < SEQ * BATCH) g_sumexp[idx] = 0.0f;
    if (idx >= SEQ * BATCH * REC) return;
    int r  = idx & (REC - 1);
    int sb = idx >> 4;
    int t  = tok[sb];
    const float4* e = (const float4*)(emb + (size_t)t * EMB);
    const float4* u = (const float4*)(U + (size_t)r * EMB);
    float acc = b1[r] + b2[r];
#pragma unroll
    for (int q = 0; q < EMB / 4; q++) {
        float4 ev = e[q], uv = u[q];
        acc = fmaf(ev.x, uv.x, acc);
        acc = fmaf(ev.y, uv.y, acc);
        acc = fmaf(ev.z, uv.z, acc);
        acc = fmaf(ev.w, uv.w, acc);
    }
    g_iproj[idx] = acc;
}

// ---------------------------------------------------------------------------
// Kernel 2: sequential recurrence (single CTA), unchanged.
// ---------------------------------------------------------------------------
__global__ void __launch_bounds__(256) rnn_kernel(const float* __restrict__ W,
                                                  const float* __restrict__ h0) {
    __shared__ float2 hd[2][REC][17];
    int tid = threadIdx.x;
    int bp  = tid >> 4;
    int r   = tid & (REC - 1);

    float2 wdup[REC];
#pragma unroll
    for (int j = 0; j < REC; j++) {
        float w = W[r * REC + j];
        wdup[j] = make_float2(w, w);
    }

    float c0 = h0[r], c1 = c0;
    hd[0][r][bp] = make_float2(c0, c1);
    __syncthreads();

    const int base = bp * 2 * REC + r;

    float ip0[2], ip1[2];
    ip0[0] = g_iproj[0 * 512 + base];  ip1[0] = g_iproj[0 * 512 + base + REC];
    ip0[1] = g_iproj[1 * 512 + base];  ip1[1] = g_iproj[1 * 512 + base + REC];

    for (int t = 0; t < SEQ; t++) {
        g_hidden[t * 512 + base]       = c0;
        g_hidden[t * 512 + base + REC] = c1;

        if (t < SEQ - 1) {
            int rb = t & 1, wb = rb ^ 1;
            float2 acc = make_float2(ip0[rb], ip1[rb]);
            if (t + 2 < SEQ) {
                ip0[rb] = g_iproj[(t + 2) * 512 + base];
                ip1[rb] = g_iproj[(t + 2) * 512 + base + REC];
            }
#pragma unroll
            for (int j = 0; j < REC; j++)
                acc = ffma2(hd[rb][j][bp], wdup[j], acc);
            float e0 = __expf(2.0f * acc.x);
            float e1 = __expf(2.0f * acc.y);
            c0 = 1.0f - __fdividef(2.0f, e0 + 1.0f);
            c1 = 1.0f - __fdividef(2.0f, e1 + 1.0f);
            hd[wb][r][bp] = make_float2(c0, c1);
        }
        __syncthreads();
    }
}

// Build A fragments (h, batch-as-M): 2 m-tiles (batch 0-15, 16-31).
__device__ __forceinline__ void make_afrags(uint32_t a[2][4], int s, int g, int t) {
    const float* hb = g_hidden + s * 512;
#pragma unroll
    for (int m = 0; m < 2; m++) {
        int r0 = m * 16 + g, r1 = m * 16 + g + 8;
        float2 x0 = *(const float2*)(hb + r0 * REC + 2 * t);
        float2 x1 = *(const float2*)(hb + r1 * REC + 2 * t);
        float2 x2 = *(const float2*)(hb + r0 * REC + 2 * t + 8);
        float2 x3 = *(const float2*)(hb + r1 * REC + 2 * t + 8);
        a[m][0] = pk2(x0.x, x0.y);
        a[m][1] = pk2(x1.x, x1.y);
        a[m][2] = pk2(x2.x, x2.y);
        a[m][3] = pk2(x3.x, x3.y);
    }
}

// ---------------------------------------------------------------------------
// Kernel 3a: sum of exp(logit). grid(SLICES_A, SEQ), 256 threads.
// (unchanged from R10 — measured at the MUFU floor)
// ---------------------------------------------------------------------------
__global__ void __launch_bounds__(256) sumexp_mma_kernel() {
    const int slice = blockIdx.x;
    const int s     = blockIdx.y;
    const int tid   = threadIdx.x;
    const int wid   = tid >> 5, lane = tid & 31;
    const int g = lane >> 2, t = lane & 3;

    uint32_t a[2][4];
    make_afrags(a, s, g, t);

    float acc[4] = {0.f, 0.f, 0.f, 0.f};   // batch rows g, g+8, g+16, g+24

    const int tile0 = slice * TPC_A + wid * TPW_A;
    const uint2* bp = &g_Vmma[(size_t)tile0 * 32 + lane];

    for (int i = 0; i < TPW_A; i++) {
        uint2 b = bp[i * 32];
        float d0[4] = {0.f, 0.f, 0.f, 0.f};
        float d1[4] = {0.f, 0.f, 0.f, 0.f};
        mma16816(d0, a[0], b.x, b.y);
        mma16816(d1, a[1], b.x, b.y);
        acc[0] += __expf(d0[0]) + __expf(d0[1]);
        acc[1] += __expf(d0[2]) + __expf(d0[3]);
        acc[2] += __expf(d1[0]) + __expf(d1[1]);
        acc[3] += __expf(d1[2]) + __expf(d1[3]);
    }

#pragma unroll
    for (int k = 0; k < 4; k++) {
        float v = acc[k];
        v += __shfl_xor_sync(0xffffffffu, v, 1);
        v += __shfl_xor_sync(0xffffffffu, v, 2);
        acc[k] = v;
    }

    __shared__ float red[8][BATCH];
    if (t == 0) {
        red[wid][g]      = acc[0];
        red[wid][g + 8]  = acc[1];
        red[wid][g + 16] = acc[2];
        red[wid][g + 24] = acc[3];
    }
    __syncthreads();
    if (tid < BATCH) {
        float tot = 0.f;
#pragma unroll
        for (int w = 0; w < 8; w++) tot += red[w][tid];
        atomicAdd(&g_sumexp[s * BATCH + tid], tot);
    }
}

// ---------------------------------------------------------------------------
// Kernel 3b: recompute logits, write log_softmax with smem-transposed,
// fully-coalesced stores. grid(SLICES_B, SEQ), 256 threads / 8 warps.
// Each warp per chunk: 4 n-tiles = 32 vocab x 32 batch staged in
// buf[32][36] (rows 16B-aligned), then 8x (LDS.128 + STG.128): each
// STG.128 instruction writes 4 batch rows x 128B contiguous.
// ---------------------------------------------------------------------------
__global__ void __launch_bounds__(256) write_mma_kernel(float* __restrict__ out) {
    __shared__ float buf[8][32][36];
    const int slice = blockIdx.x;
    const int s     = blockIdx.y;
    const int tid   = threadIdx.x;
    const int wid   = tid >> 5, lane = tid & 31;
    const int g = lane >> 2, t = lane & 3;

    uint32_t a[2][4];
    make_afrags(a, s, g, t);

    const float* se = g_sumexp + s * BATCH;
    const float nz0 = -__logf(se[g]);
    const float nz1 = -__logf(se[g + 8]);
    const float nz2 = -__logf(se[g + 16]);
    const float nz3 = -__logf(se[g + 24]);

    float* obase = out + (size_t)s * BATCH * VOCAB;
    float (*wb)[36] = buf[wid];

    const int rrow = lane >> 3;          // readout row-in-group 0..3
    const int rcol = (lane & 7) * 4;     // readout col 0..28

    for (int i = 0; i < CPW_B; i++) {
        const int chunk = slice * CPC_B + i * 8 + wid;
        const int v0 = chunk * 32;

#pragma unroll
        for (int j = 0; j < 4; j++) {
            uint2 b = g_Vmma[(size_t)(chunk * 4 + j) * 32 + lane];
            float d0[4] = {nz0, nz0, nz1, nz1};
            float d1[4] = {nz2, nz2, nz3, nz3};
            mma16816(d0, a[0], b.x, b.y);
            mma16816(d1, a[1], b.x, b.y);
            const int col = j * 8 + 2 * t;
            *(float2*)&wb[g][col]      = make_float2(d0[0], d0[1]);
            *(float2*)&wb[g + 8][col]  = make_float2(d0[2], d0[3]);
            *(float2*)&wb[g + 16][col] = make_float2(d1[0], d1[1]);
            *(float2*)&wb[g + 24][col] = make_float2(d1[2], d1[3]);
        }
        __syncwarp();

#pragma unroll
        for (int it = 0; it < 8; it++) {
            const int row = it * 4 + rrow;
            float4 x = *(float4*)&wb[row][rcol];
            *(float4*)(obase + (size_t)row * VOCAB + v0 + rcol) = x;
        }
        __syncwarp();
    }
}

// ---------------------------------------------------------------------------
extern "C" void kernel_launch(void* const* d_in, const int* in_sizes, int n_in,
                              void* d_out, int out_size) {
    const int*   tok = (const int*)  d_in[0];
    const float* emb = (const float*)d_in[1];
    const float* U   = (const float*)d_in[2];
    const float* W   = (const float*)d_in[3];
    const float* V   = (const float*)d_in[4];
    const float* b1  = (const float*)d_in[5];
    const float* b2  = (const float*)d_in[6];
    const float* h0  = (const float*)d_in[7];
    float* out = (float*)d_out;

    vprep_kernel<<<(NT8 * 32 + 255) / 256, 256>>>(V);
    iproj_kernel<<<(SEQ * BATCH * REC + 255) / 256, 256>>>(tok, emb, U, b1, b2);
    rnn_kernel<<<1, 256>>>(W, h0);
    dim3 gridA(SLICES_A, SEQ);
    sumexp_mma_kernel<<<gridA, 256>>>();
    dim3 gridB(SLICES_B, SEQ);
    write_mma_kernel<<<gridB, 256>>>(out);
}

// round 13
// speedup vs baseline: 1.1467x; 1.0137x over previous
#include <cuda_runtime.h>
#include <cuda_bf16.h>
#include <cstdint>
#include <cstddef>

#define VOCAB 32000
#define EMB   32
#define REC   16
#define SEQ   256
#define BATCH 32

#define NT8 (VOCAB / 8)              // 4000 vocab n-tiles of 8 rows

// role A (sumexp): 10 slices -> 400 tiles/CTA, 50/warp
#define SLICES_A 10
#define TPC_A    (NT8 / SLICES_A)
#define TPW_A    (TPC_A / 8)
#define TOTAL_A  (SLICES_A * SEQ)    // 2560 CTAs

// role B (write): chunks of 32 vocab (4 n-tiles). 1000 chunks per s.
#define NCHUNKS   (VOCAB / 32)       // 1000
#define SLICES_B  25
#define CPC_B     (NCHUNKS / SLICES_B)   // 40 chunks/CTA
#define CPW_B     (CPC_B / 8)            // 5 chunks/warp
#define TOTAL_B   (SLICES_B * SEQ)       // 6400 CTAs

// Scratch (allocation-free rule: __device__ globals)
__device__ float g_hidden[SEQ * BATCH * REC];
__device__ float g_iproj [SEQ * BATCH * REC];
__device__ float g_sumexp[SEQ * BATCH];
__device__ int   g_done  [SEQ];
__device__ uint2 g_Vmma  [NT8 * 32];   // V as B-operand fragments, lane-ordered

// ---------------------------------------------------------------------------
// helpers
// ---------------------------------------------------------------------------
__device__ __forceinline__ float2 ffma2(float2 a, float2 b, float2 c) {
    union { float2 f; unsigned long long u; } A, B, C, D;
    A.f = a; B.f = b; C.f = c;
    asm("fma.rn.f32x2 %0, %1, %2, %3;" : "=l"(D.u) : "l"(A.u), "l"(B.u), "l"(C.u));
    return D.f;
}

__device__ __forceinline__ uint32_t pk2(float a, float b) {
    __nv_bfloat162 t = __float22bfloat162_rn(make_float2(a, b));
    return *reinterpret_cast<uint32_t*>(&t);
}

// D(16x8,f32) = A(16x16,bf16,row) * B(16x8,bf16,col) + D   — base-ISA HMMA
__device__ __forceinline__ void mma16816(float* d, const uint32_t* a,
                                         uint32_t b0, uint32_t b1) {
    asm volatile(
        "mma.sync.aligned.m16n8k16.row.col.f32.bf16.bf16.f32 "
        "{%0,%1,%2,%3}, {%4,%5,%6,%7}, {%8,%9}, {%0,%1,%2,%3};"
        : "+f"(d[0]), "+f"(d[1]), "+f"(d[2]), "+f"(d[3])
        : "r"(a[0]), "r"(a[1]), "r"(a[2]), "r"(a[3]), "r"(b0), "r"(b1));
}

// ---------------------------------------------------------------------------
// Kernel 0: pack V into B-operand fragments.
// ---------------------------------------------------------------------------
__global__ void vprep_kernel(const float* __restrict__ V) {
    int idx = blockIdx.x * blockDim.x + threadIdx.x;
    if (idx >= NT8 * 32) return;
    int tile = idx >> 5, lane = idx & 31;
    int g = lane >> 2, t = lane & 3;
    const float* r = V + (size_t)(tile * 8 + g) * REC;
    uint2 b;
    b.x = pk2(r[2 * t],     r[2 * t + 1]);
    b.y = pk2(r[2 * t + 8], r[2 * t + 9]);
    g_Vmma[idx] = b;
}

// ---------------------------------------------------------------------------
// Kernel 1: input projection + zero g_sumexp / g_done.
// ---------------------------------------------------------------------------
__global__ void iproj_kernel(const int* __restrict__ tok,
                             const float* __restrict__ emb,
                             const float* __restrict__ U,
                             const float* __restrict__ b1,
                             const float* __restrict__ b2) {
    int idx = blockIdx.x * blockDim.x + threadIdx.x;
    if (idx < SEQ * BATCH) g_sumexp[idx] = 0.0f;
    if (idx < SEQ) g_done[idx] = 0;
    if (idx >= SEQ * BATCH * REC) return;
    int r  = idx & (REC - 1);
    int sb = idx >> 4;
    int t  = tok[sb];
    const float4* e = (const float4*)(emb + (size_t)t * EMB);
    const float4* u = (const float4*)(U + (size_t)r * EMB);
    float acc = b1[r] + b2[r];
#pragma unroll
    for (int q = 0; q < EMB / 4; q++) {
        float4 ev = e[q], uv = u[q];
        acc = fmaf(ev.x, uv.x, acc);
        acc = fmaf(ev.y, uv.y, acc);
        acc = fmaf(ev.z, uv.z, acc);
        acc = fmaf(ev.w, uv.w, acc);
    }
    g_iproj[idx] = acc;
}

// ---------------------------------------------------------------------------
// Kernel 2: sequential recurrence (single CTA), unchanged.
// ---------------------------------------------------------------------------
__global__ void __launch_bounds__(256) rnn_kernel(const float* __restrict__ W,
                                                  const float* __restrict__ h0) {
    __shared__ float2 hd[2][REC][17];
    int tid = threadIdx.x;
    int bp  = tid >> 4;
    int r   = tid & (REC - 1);

    float2 wdup[REC];
#pragma unroll
    for (int j = 0; j < REC; j++) {
        float w = W[r * REC + j];
        wdup[j] = make_float2(w, w);
    }

    float c0 = h0[r], c1 = c0;
    hd[0][r][bp] = make_float2(c0, c1);
    __syncthreads();

    const int base = bp * 2 * REC + r;

    float ip0[2], ip1[2];
    ip0[0] = g_iproj[0 * 512 + base];  ip1[0] = g_iproj[0 * 512 + base + REC];
    ip0[1] = g_iproj[1 * 512 + base];  ip1[1] = g_iproj[1 * 512 + base + REC];

    for (int t = 0; t < SEQ; t++) {
        g_hidden[t * 512 + base]       = c0;
        g_hidden[t * 512 + base + REC] = c1;

        if (t < SEQ - 1) {
            int rb = t & 1, wb = rb ^ 1;
            float2 acc = make_float2(ip0[rb], ip1[rb]);
            if (t + 2 < SEQ) {
                ip0[rb] = g_iproj[(t + 2) * 512 + base];
                ip1[rb] = g_iproj[(t + 2) * 512 + base + REC];
            }
#pragma unroll
            for (int j = 0; j < REC; j++)
                acc = ffma2(hd[rb][j][bp], wdup[j], acc);
            float e0 = __expf(2.0f * acc.x);
            float e1 = __expf(2.0f * acc.y);
            c0 = 1.0f - __fdividef(2.0f, e0 + 1.0f);
            c1 = 1.0f - __fdividef(2.0f, e1 + 1.0f);
            hd[wb][r][bp] = make_float2(c0, c1);
        }
        __syncthreads();
    }
}

// Build A fragments (h, batch-as-M): 2 m-tiles (batch 0-15, 16-31).
__device__ __forceinline__ void make_afrags(uint32_t a[2][4], int s, int g, int t) {
    const float* hb = g_hidden + s * 512;
#pragma unroll
    for (int m = 0; m < 2; m++) {
        int r0 = m * 16 + g, r1 = m * 16 + g + 8;
        float2 x0 = *(const float2*)(hb + r0 * REC + 2 * t);
        float2 x1 = *(const float2*)(hb + r1 * REC + 2 * t);
        float2 x2 = *(const float2*)(hb + r0 * REC + 2 * t + 8);
        float2 x3 = *(const float2*)(hb + r1 * REC + 2 * t + 8);
        a[m][0] = pk2(x0.x, x0.y);
        a[m][1] = pk2(x1.x, x1.y);
        a[m][2] = pk2(x2.x, x2.y);
        a[m][3] = pk2(x3.x, x3.y);
    }
}

// ---------------------------------------------------------------------------
// Kernel 3 (FUSED): roles by blockIdx.x.
//   [0, TOTAL_A):        sumexp role (identical to proven R10 kernel);
//                        signals g_done[s] when its partial is committed.
//   [TOTAL_A, +TOTAL_B): write role; spins until g_done[s]==SLICES_A, then
//                        identical to proven R11 write kernel.
// All sumexp bids precede write bids -> dispatch order guarantees progress.
// ---------------------------------------------------------------------------
__global__ void __launch_bounds__(256) fused_kernel(float* __restrict__ out) {
    __shared__ float buf[8][32][36];            // write role staging
    const int bid = blockIdx.x;
    const int tid = threadIdx.x;
    const int wid = tid >> 5, lane = tid & 31;
    const int g = lane >> 2, t = lane & 3;

    if (bid < TOTAL_A) {
        // ---------------- sumexp role ----------------
        const int slice = bid % SLICES_A;
        const int s     = bid / SLICES_A;

        uint32_t a[2][4];
        make_afrags(a, s, g, t);

        float acc[4] = {0.f, 0.f, 0.f, 0.f};
        const int tile0 = slice * TPC_A + wid * TPW_A;
        const uint2* bp = &g_Vmma[(size_t)tile0 * 32 + lane];

        for (int i = 0; i < TPW_A; i++) {
            uint2 b = bp[i * 32];
            float d0[4] = {0.f, 0.f, 0.f, 0.f};
            float d1[4] = {0.f, 0.f, 0.f, 0.f};
            mma16816(d0, a[0], b.x, b.y);
            mma16816(d1, a[1], b.x, b.y);
            acc[0] += __expf(d0[0]) + __expf(d0[1]);
            acc[1] += __expf(d0[2]) + __expf(d0[3]);
            acc[2] += __expf(d1[0]) + __expf(d1[1]);
            acc[3] += __expf(d1[2]) + __expf(d1[3]);
        }

#pragma unroll
        for (int k = 0; k < 4; k++) {
            float v = acc[k];
            v += __shfl_xor_sync(0xffffffffu, v, 1);
            v += __shfl_xor_sync(0xffffffffu, v, 2);
            acc[k] = v;
        }

        float (*red)[BATCH] = (float (*)[BATCH])buf;   // alias staging smem
        if (t == 0) {
            red[wid][g]      = acc[0];
            red[wid][g + 8]  = acc[1];
            red[wid][g + 16] = acc[2];
            red[wid][g + 24] = acc[3];
        }
        __syncthreads();
        if (tid < BATCH) {
            float tot = 0.f;
#pragma unroll
            for (int w = 0; w < 8; w++) tot += red[w][tid];
            atomicAdd(&g_sumexp[s * BATCH + tid], tot);
        }
        __syncthreads();
        if (tid == 0) {
            __threadfence();
            atomicAdd(&g_done[s], 1);
        }
    } else {
        // ---------------- write role ----------------
        const int j     = bid - TOTAL_A;
        const int slice = j % SLICES_B;
        const int s     = j / SLICES_B;

        uint32_t a[2][4];
        make_afrags(a, s, g, t);

        if (tid == 0) {
            while (atomicAdd(&g_done[s], 0) < SLICES_A) __nanosleep(256);
        }
        __syncthreads();
        __threadfence();

        const float* se = g_sumexp + s * BATCH;
        const float nz0 = -__logf(se[g]);
        const float nz1 = -__logf(se[g + 8]);
        const float nz2 = -__logf(se[g + 16]);
        const float nz3 = -__logf(se[g + 24]);

        float* obase = out + (size_t)s * BATCH * VOCAB;
        float (*wb)[36] = buf[wid];

        const int rrow = lane >> 3;          // readout row-in-group 0..3
        const int rcol = (lane & 7) * 4;     // readout col 0..28

        for (int i = 0; i < CPW_B; i++) {
            const int chunk = slice * CPC_B + i * 8 + wid;
            const int v0 = chunk * 32;

#pragma unroll
            for (int jj = 0; jj < 4; jj++) {
                uint2 b = g_Vmma[(size_t)(chunk * 4 + jj) * 32 + lane];
                float d0[4] = {nz0, nz0, nz1, nz1};
                float d1[4] = {nz2, nz2, nz3, nz3};
                mma16816(d0, a[0], b.x, b.y);
                mma16816(d1, a[1], b.x, b.y);
                const int col = jj * 8 + 2 * t;
                *(float2*)&wb[g][col]      = make_float2(d0[0], d0[1]);
                *(float2*)&wb[g + 8][col]  = make_float2(d0[2], d0[3]);
                *(float2*)&wb[g + 16][col] = make_float2(d1[0], d1[1]);
                *(float2*)&wb[g + 24][col] = make_float2(d1[2], d1[3]);
            }
            __syncwarp();

#pragma unroll
            for (int it = 0; it < 8; it++) {
                const int row = it * 4 + rrow;
                float4 x = *(float4*)&wb[row][rcol];
                *(float4*)(obase + (size_t)row * VOCAB + v0 + rcol) = x;
            }
            __syncwarp();
        }
    }
}

// ---------------------------------------------------------------------------
extern "C" void kernel_launch(void* const* d_in, const int* in_sizes, int n_in,
                              void* d_out, int out_size) {
    const int*   tok = (const int*)  d_in[0];
    const float* emb = (const float*)d_in[1];
    const float* U   = (const float*)d_in[2];
    const float* W   = (const float*)d_in[3];
    const float* V   = (const float*)d_in[4];
    const float* b1  = (const float*)d_in[5];
    const float* b2  = (const float*)d_in[6];
    const float* h0  = (const float*)d_in[7];
    float* out = (float*)d_out;

    vprep_kernel<<<(NT8 * 32 + 255) / 256, 256>>>(V);
    iproj_kernel<<<(SEQ * BATCH * REC + 255) / 256, 256>>>(tok, emb, U, b1, b2);
    rnn_kernel<<<1, 256>>>(W, h0);
    fused_kernel<<<TOTAL_A + TOTAL_B, 256>>>(out);
}